// round 9
// baseline (speedup 1.0000x reference)
#include <cuda_runtime.h>
#include <cstdint>

// Problem constants
#define B_   1024
#define T_   512
#define I_   16
#define H_   50
#define G_   200      // 4*H
#define FCD  64
#define NB   7        // rows per block -> grid 147, single wave
#define NTH  448      // 14 warps: warps 0-6 group A, warps 7-13 group B
#define NC1  (NB * H_)        // 350
#define NCELL (2 * NB * H_)   // 700

typedef unsigned long long ull;

// Precomputed bias-folded x-gates for layer 1: [t][b][g]. Padding covers the
// boundary block's over-read (rows 1024..1028, finite values, never output).
__device__ float g_gx[(size_t)T_ * B_ * G_ + 4096];

// ---- f32x2 packed helpers (sm_103a FFMA2) ----
__device__ __forceinline__ void fma2(ull& acc, ull a, ull b) {
    asm("fma.rn.f32x2 %0, %1, %2, %0;" : "+l"(acc) : "l"(a), "l"(b));
}
__device__ __forceinline__ ull pk2(float x, float y) {
    ull r;
    asm("mov.b64 %0, {%1, %2};" : "=l"(r) : "f"(x), "f"(y));
    return r;
}
__device__ __forceinline__ float rsum(ull v) {
    float2 r;
    asm("mov.b64 {%0, %1}, %2;" : "=f"(r.x), "=f"(r.y) : "l"(v));
    return r.x + r.y;
}

// ---- fast activations: single-MUFU ex2 / rcp ----
__device__ __forceinline__ float fex2(float x) {
    float r;
    asm("ex2.approx.f32 %0, %1;" : "=f"(r) : "f"(x));
    return r;
}
__device__ __forceinline__ float frcp(float x) {
    float r;
    asm("rcp.approx.f32 %0, %1;" : "=f"(r) : "f"(x));
    return r;
}
#define LOG2E  1.4426950408889634f
__device__ __forceinline__ float sigf(float x) {
    return frcp(1.0f + fex2(-LOG2E * x));
}
__device__ __forceinline__ float tanh_f(float x) {
    return 2.0f * frcp(1.0f + fex2(-2.0f * LOG2E * x)) - 1.0f;
}

// ============================================================================
// Kernel 1: gx[t][b][g] = b_ih0[g] + b_hh0[g] + x[b,t,:] . w_ih0[g,:]
// ============================================================================
#define TT 128
__global__ __launch_bounds__(256, 4)
void xgate_kernel(const float* __restrict__ x,
                  const float* __restrict__ w_ih0,
                  const float* __restrict__ b_ih0,
                  const float* __restrict__ b_hh0) {
    __shared__ __align__(16) float xs[TT][I_];   // 8 KB
    const int b   = blockIdx.y;
    const int t0  = blockIdx.x * TT;
    const int tid = threadIdx.x;

    const float4* src = (const float4*)(x + ((size_t)b * T_ + t0) * I_);
    ((float4*)xs)[tid]       = src[tid];
    ((float4*)xs)[tid + 256] = src[tid + 256];
    __syncthreads();

    if (tid < G_) {
        ull w[8];
        #pragma unroll
        for (int k2 = 0; k2 < 8; k2++)
            w[k2] = pk2(__ldg(&w_ih0[tid * I_ + 2 * k2]),
                        __ldg(&w_ih0[tid * I_ + 2 * k2 + 1]));
        const float bias = __ldg(&b_ih0[tid]) + __ldg(&b_hh0[tid]);
        for (int tt = 0; tt < TT; tt++) {
            ull acc = pk2(bias, 0.0f);
            #pragma unroll
            for (int q = 0; q < 4; q++) {
                const ulonglong2 v = *(const ulonglong2*)&xs[tt][4 * q];
                fma2(acc, w[2 * q],     v.x);
                fma2(acc, w[2 * q + 1], v.y);
            }
            g_gx[((size_t)(t0 + tt) * B_ + b) * G_ + tid] = rsum(acc);
        }
    }
}

// ============================================================================
// Kernel 2: fused 2-layer LSTM recurrence + FC head. 448 threads.
// iter it: L1 step it (gx[it], h1_{it-1});  L2 step it-1 (h1_{it-1}, h2_{it-2})
// Group A (warps 0-6):  gl1 = gx + Whh0.h1 ;  pA = Wih1[chunks 0..11].h1
//   -> the SAME 13 h1 quad-loads feed 38 FFMA2 (2:3 load:fma ratio halved)
// Group B (warps 7-13): pB = bias2 + Wih1[chunks 12..25].h1 + Whh1.h2
// L2 gate = pA + pB. gx prefetched one iteration ahead via plain LDG (regs).
// ============================================================================
__global__ __launch_bounds__(NTH, 1)
void fused_lstm_kernel(const float* __restrict__ w_hh0,  // [G, H]
                       const float* __restrict__ w_ih1,  // [G, H]
                       const float* __restrict__ w_hh1,  // [G, H]
                       const float* __restrict__ b_ih1,
                       const float* __restrict__ b_hh1,
                       const float* __restrict__ fc1_w,  // [FC, H]
                       const float* __restrict__ fc1_b,
                       const float* __restrict__ fc2_w,  // [1, FC]
                       const float* __restrict__ fc2_b,
                       float* __restrict__ out)          // [B, 1]
{
    __shared__ __align__(16) float hx[2][NB][52];   // [0]=h1, [1]=h2 (padded)
    __shared__ float gl1[NB][G_];                   // L1 gates (complete)
    __shared__ float pA[NB][G_];                    // L2 partial from group A
    __shared__ float pB[NB][G_];                    // L2 partial from group B

    const int tid  = threadIdx.x;
    const int row0 = blockIdx.x * NB;
    const bool grpA = (tid < 224);
    const int  g    = grpA ? tid : tid - 224;
    const bool isG  = (g < G_);

    // ---- weights (f32x2 packed, zero-padded) ----
    ull wh0[26], wi1lo[12];    // group A: 38 ull
    ull wi1hi[14], wh1[26];    // group B: 40 ull
    float bias2 = 0.0f;
    if (isG) {
        if (grpA) {
            #pragma unroll
            for (int k2 = 0; k2 < 26; k2++) {
                float a0 = (2 * k2     < H_) ? __ldg(&w_hh0[g * H_ + 2 * k2])     : 0.0f;
                float a1 = (2 * k2 + 1 < H_) ? __ldg(&w_hh0[g * H_ + 2 * k2 + 1]) : 0.0f;
                wh0[k2] = pk2(a0, a1);
            }
            #pragma unroll
            for (int k2 = 0; k2 < 12; k2++)
                wi1lo[k2] = pk2(__ldg(&w_ih1[g * H_ + 2 * k2]),
                                __ldg(&w_ih1[g * H_ + 2 * k2 + 1]));
        } else {
            #pragma unroll
            for (int k2 = 12; k2 < 26; k2++) {
                float a0 = (2 * k2     < H_) ? __ldg(&w_ih1[g * H_ + 2 * k2])     : 0.0f;
                float a1 = (2 * k2 + 1 < H_) ? __ldg(&w_ih1[g * H_ + 2 * k2 + 1]) : 0.0f;
                wi1hi[k2 - 12] = pk2(a0, a1);
            }
            #pragma unroll
            for (int k2 = 0; k2 < 26; k2++) {
                float a0 = (2 * k2     < H_) ? __ldg(&w_hh1[g * H_ + 2 * k2])     : 0.0f;
                float a1 = (2 * k2 + 1 < H_) ? __ldg(&w_hh1[g * H_ + 2 * k2 + 1]) : 0.0f;
                wh1[k2] = pk2(a0, a1);
            }
            bias2 = __ldg(&b_ih1[g]) + __ldg(&b_hh1[g]);
        }
    }

    // gx prefetch registers (group A gate threads): current iter's values
    float gxr[NB];
    if (grpA && isG) {
        #pragma unroll
        for (int r = 0; r < NB; r++)
            gxr[r] = __ldg(&g_gx[(size_t)(row0 + r) * G_ + g]);   // t = 0
    }

    // ---- zero h buffers (pads must stay 0) ----
    for (int i = tid; i < 2 * NB * 52; i += NTH) ((float*)hx)[i] = 0.0f;

    // ---- combine ownership ----
    // k=0: cell tid (tid<448 < NCELL=700, always valid)
    // k=1: cells 448..699 owned by tid 196..447 (cell = tid + 252)
    float c_st[2] = {0.0f, 0.0f};
    int   coff[2], hoff[2];
    bool  cl2[2];
    const bool has2 = (tid >= 196);
    #pragma unroll
    for (int k = 0; k < 2; k++) {
        const int cell = (k == 0) ? tid : (has2 ? tid + 252 : 0);
        cl2[k] = (cell >= NC1);
        const int rem = cl2[k] ? cell - NC1 : cell;
        const int r = rem / H_;
        const int j = rem - r * H_;
        coff[k] = r * G_ + j;
        hoff[k] = (cl2[k] ? NB * 52 : 0) + r * 52 + j;
    }
    __syncthreads();

    for (int it = 0; it <= T_; it++) {
        // ---- gate phase ----
        if (isG) {
            if (grpA) {
                // prefetch next iteration's gx (latency hidden by this iter)
                float gxn[NB];
                if (it + 1 < T_) {
                    #pragma unroll
                    for (int r = 0; r < NB; r++)
                        gxn[r] = __ldg(&g_gx[((size_t)(it + 1) * B_ + row0 + r) * G_ + g]);
                }
                #pragma unroll
                for (int r = 0; r < NB; r++) {
                    ull e0 = pk2(gxr[r], 0.0f), o0 = 0ull;
                    ull e1 = 0ull,              o1 = 0ull;
                    // batch 1: h1 quads 0..6 -> feeds Whh0 (14) + Wih1lo (12)
                    ulonglong2 v[7];
                    #pragma unroll
                    for (int q = 0; q < 7; q++)
                        v[q] = *(const ulonglong2*)&hx[0][r][4 * q];
                    #pragma unroll
                    for (int q = 0; q < 7; q++) {
                        fma2(e0, wh0[2 * q],     v[q].x);
                        fma2(o0, wh0[2 * q + 1], v[q].y);
                    }
                    #pragma unroll
                    for (int q = 0; q < 6; q++) {
                        fma2(e1, wi1lo[2 * q],     v[q].x);
                        fma2(o1, wi1lo[2 * q + 1], v[q].y);
                    }
                    // batch 2: h1 quads 7..12 -> Whh0 (12)
                    ulonglong2 u[6];
                    #pragma unroll
                    for (int q = 0; q < 6; q++)
                        u[q] = *(const ulonglong2*)&hx[0][r][4 * (q + 7)];
                    #pragma unroll
                    for (int q = 0; q < 6; q++) {
                        fma2(e0, wh0[2 * (q + 7)],     u[q].x);
                        fma2(o0, wh0[2 * (q + 7) + 1], u[q].y);
                    }
                    gl1[r][g] = rsum(e0) + rsum(o0);
                    pA[r][g]  = rsum(e1) + rsum(o1);
                }
                if (it + 1 < T_) {
                    #pragma unroll
                    for (int r = 0; r < NB; r++) gxr[r] = gxn[r];
                }
            } else {
                #pragma unroll
                for (int r = 0; r < NB; r++) {
                    ull e = pk2(bias2, 0.0f), o = 0ull;
                    // batch 1: h1 quads 6..12 -> Wih1hi (14)
                    ulonglong2 v[7];
                    #pragma unroll
                    for (int q = 0; q < 7; q++)
                        v[q] = *(const ulonglong2*)&hx[0][r][4 * (q + 6)];
                    #pragma unroll
                    for (int q = 0; q < 7; q++) {
                        fma2(e, wi1hi[2 * q],     v[q].x);
                        fma2(o, wi1hi[2 * q + 1], v[q].y);
                    }
                    // batch 2: h2 quads 0..6 -> Whh1 (14)
                    #pragma unroll
                    for (int q = 0; q < 7; q++)
                        v[q] = *(const ulonglong2*)&hx[1][r][4 * q];
                    #pragma unroll
                    for (int q = 0; q < 7; q++) {
                        fma2(e, wh1[2 * q],     v[q].x);
                        fma2(o, wh1[2 * q + 1], v[q].y);
                    }
                    // batch 3: h2 quads 7..12 -> Whh1 (12)
                    ulonglong2 u[6];
                    #pragma unroll
                    for (int q = 0; q < 6; q++)
                        u[q] = *(const ulonglong2*)&hx[1][r][4 * (q + 7)];
                    #pragma unroll
                    for (int q = 0; q < 6; q++) {
                        fma2(e, wh1[2 * (q + 7)],     u[q].x);
                        fma2(o, wh1[2 * (q + 7) + 1], u[q].y);
                    }
                    pB[r][g] = rsum(e) + rsum(o);
                }
            }
        }
        __syncthreads();

        // ---- combine: 1-2 cells per thread (gate order i, f, g, o) ----
        #pragma unroll
        for (int k = 0; k < 2; k++) {
            const bool own = (k == 0) || has2;
            if (own) {
                const bool act = cl2[k] ? (it >= 1) : (it < T_);
                if (act) {
                    const int o = coff[k];
                    float gi, gf, gg, go;
                    if (cl2[k]) {
                        const float* q1 = &pA[0][0];
                        const float* q2 = &pB[0][0];
                        gi = q1[o]           + q2[o];
                        gf = q1[o + H_]      + q2[o + H_];
                        gg = q1[o + 2 * H_]  + q2[o + 2 * H_];
                        go = q1[o + 3 * H_]  + q2[o + 3 * H_];
                    } else {
                        const float* q0 = &gl1[0][0];
                        gi = q0[o];
                        gf = q0[o + H_];
                        gg = q0[o + 2 * H_];
                        go = q0[o + 3 * H_];
                    }
                    const float ig = sigf(gi);
                    const float fg = sigf(gf);
                    const float gv = tanh_f(gg);
                    const float og = sigf(go);
                    c_st[k] = fg * c_st[k] + ig * gv;
                    ((float*)hx)[hoff[k]] = og * tanh_f(c_st[k]);
                }
            }
        }
        __syncthreads();
    }

    // ---- FC head: warps 0-6 each handle one batch row, shfl reduction ----
    const int wid  = tid / 32;
    const int lane = tid - wid * 32;
    if (wid < NB) {
        const int row = row0 + wid;
        if (row < B_) {
            float s = 0.0f;
            #pragma unroll
            for (int uu = 0; uu < 2; uu++) {
                const int u = lane + uu * 32;
                float a = __ldg(&fc1_b[u]);
                #pragma unroll
                for (int k = 0; k < H_; k++)
                    a += __ldg(&fc1_w[u * H_ + k]) * hx[1][wid][k];
                a = fmaxf(a, 0.0f);
                s += a * __ldg(&fc2_w[u]);
            }
            #pragma unroll
            for (int off = 16; off > 0; off >>= 1)
                s += __shfl_down_sync(0xffffffffu, s, off);
            if (lane == 0) out[row] = s + __ldg(&fc2_b[0]);
        }
    }
}

extern "C" void kernel_launch(void* const* d_in, const int* in_sizes, int n_in,
                              void* d_out, int out_size) {
    const float* x     = (const float*)d_in[0];
    const float* w_ih0 = (const float*)d_in[1];
    const float* w_hh0 = (const float*)d_in[2];
    const float* b_ih0 = (const float*)d_in[3];
    const float* b_hh0 = (const float*)d_in[4];
    const float* w_ih1 = (const float*)d_in[5];
    const float* w_hh1 = (const float*)d_in[6];
    const float* b_ih1 = (const float*)d_in[7];
    const float* b_hh1 = (const float*)d_in[8];
    const float* fc1_w = (const float*)d_in[9];
    const float* fc1_b = (const float*)d_in[10];
    const float* fc2_w = (const float*)d_in[11];
    const float* fc2_b = (const float*)d_in[12];
    float* out = (float*)d_out;

    dim3 xg_grid(T_ / TT, B_);
    xgate_kernel<<<xg_grid, 256>>>(x, w_ih0, b_ih0, b_hh0);

    const int grid = (B_ + NB - 1) / NB;   // 147
    fused_lstm_kernel<<<grid, NTH>>>(
        w_hh0, w_ih1, w_hh1, b_ih1, b_hh1,
        fc1_w, fc1_b, fc2_w, fc2_b, out);
}

// round 10
// speedup vs baseline: 1.2115x; 1.2115x over previous
#include <cuda_runtime.h>
#include <cstdint>

// Problem constants
#define B_   1024
#define T_   512
#define I_   16
#define H_   50
#define G_   200      // 4*H
#define FCD  64
#define NB   7        // rows per block -> grid 147, single wave
#define NTH  384      // 12 warps: 3 groups x 4 warps; 100 gate threads/group (2 gates each)
#define NC1  (NB * H_)        // 350
#define NCELL (2 * NB * H_)   // 700

typedef unsigned long long ull;

// Precomputed bias-folded x-gates for layer 1: [t][b][g]. Padding covers the
// boundary block's over-read (rows 1024..1028: reads static-zero, never output).
__device__ float g_gx[(size_t)T_ * B_ * G_ + 4096];

// ---- f32x2 packed helpers (sm_103a FFMA2) ----
__device__ __forceinline__ void fma2(ull& acc, ull a, ull b) {
    asm("fma.rn.f32x2 %0, %1, %2, %0;" : "+l"(acc) : "l"(a), "l"(b));
}
__device__ __forceinline__ ull pk2(float x, float y) {
    ull r;
    asm("mov.b64 %0, {%1, %2};" : "=l"(r) : "f"(x), "f"(y));
    return r;
}
__device__ __forceinline__ float rsum(ull v) {
    float2 r;
    asm("mov.b64 {%0, %1}, %2;" : "=f"(r.x), "=f"(r.y) : "l"(v));
    return r.x + r.y;
}

// ---- fast activations: single-MUFU ex2 / rcp ----
__device__ __forceinline__ float fex2(float x) {
    float r;
    asm("ex2.approx.f32 %0, %1;" : "=f"(r) : "f"(x));
    return r;
}
__device__ __forceinline__ float frcp(float x) {
    float r;
    asm("rcp.approx.f32 %0, %1;" : "=f"(r) : "f"(x));
    return r;
}
#define LOG2E  1.4426950408889634f
__device__ __forceinline__ float sigf(float x) {
    return frcp(1.0f + fex2(-LOG2E * x));
}
__device__ __forceinline__ float tanh_f(float x) {
    return 2.0f * frcp(1.0f + fex2(-2.0f * LOG2E * x)) - 1.0f;
}

// ============================================================================
// Kernel 1: gx[t][b][g] = b_ih0[g] + b_hh0[g] + x[b,t,:] . w_ih0[g,:]
// ============================================================================
#define TT 128
__global__ __launch_bounds__(256, 4)
void xgate_kernel(const float* __restrict__ x,
                  const float* __restrict__ w_ih0,
                  const float* __restrict__ b_ih0,
                  const float* __restrict__ b_hh0) {
    __shared__ __align__(16) float xs[TT][I_];   // 8 KB
    const int b   = blockIdx.y;
    const int t0  = blockIdx.x * TT;
    const int tid = threadIdx.x;

    const float4* src = (const float4*)(x + ((size_t)b * T_ + t0) * I_);
    ((float4*)xs)[tid]       = src[tid];
    ((float4*)xs)[tid + 256] = src[tid + 256];
    __syncthreads();

    if (tid < G_) {
        ull w[8];
        #pragma unroll
        for (int k2 = 0; k2 < 8; k2++)
            w[k2] = pk2(__ldg(&w_ih0[tid * I_ + 2 * k2]),
                        __ldg(&w_ih0[tid * I_ + 2 * k2 + 1]));
        const float bias = __ldg(&b_ih0[tid]) + __ldg(&b_hh0[tid]);
        for (int tt = 0; tt < TT; tt++) {
            ull acc = pk2(bias, 0.0f);
            #pragma unroll
            for (int q = 0; q < 4; q++) {
                const ulonglong2 v = *(const ulonglong2*)&xs[tt][4 * q];
                fma2(acc, w[2 * q],     v.x);
                fma2(acc, w[2 * q + 1], v.y);
            }
            g_gx[((size_t)(t0 + tt) * B_ + b) * G_ + tid] = rsum(acc);
        }
    }
}

// ============================================================================
// Kernel 2: fused 2-layer LSTM recurrence + FC head. 384 threads.
// iter it: L1 step it (gx[it], h1_{it-1});  L2 step it-1 (h1_{it-1}, h2_{it-2})
// 3 groups of 4 warps. Within a group, thread i < 100 computes gates 2i, 2i+1
// of ONE matrix: G0: Whh0.h1 (+gx); G1: Wih1.h1 (+bias2); G2: Whh1.h2.
// KEY: 2 gates/thread -> each broadcast LDS.128 of h feeds 4 FFMA2, halving
// the per-SM smem-crossbar traffic that bound rounds 1-9.
// ============================================================================
__global__ __launch_bounds__(NTH, 1)
void fused_lstm_kernel(const float* __restrict__ w_hh0,  // [G, H]
                       const float* __restrict__ w_ih1,  // [G, H]
                       const float* __restrict__ w_hh1,  // [G, H]
                       const float* __restrict__ b_ih1,
                       const float* __restrict__ b_hh1,
                       const float* __restrict__ fc1_w,  // [FC, H]
                       const float* __restrict__ fc1_b,
                       const float* __restrict__ fc2_w,  // [1, FC]
                       const float* __restrict__ fc2_b,
                       float* __restrict__ out)          // [B, 1]
{
    __shared__ __align__(16) float hx[2][NB][52];   // [0]=h1, [1]=h2 (padded)
    __shared__ float gl1[NB][G_];                   // L1 gates (complete)
    __shared__ float pA[NB][G_];                    // L2 partial (Wih1 part)
    __shared__ float pB[NB][G_];                    // L2 partial (Whh1 part)

    const int tid  = threadIdx.x;
    const int row0 = blockIdx.x * NB;
    const int grp  = tid >> 7;             // 0/1/2 (128 threads each)
    const int i    = tid & 127;            // index within group
    const bool isG = (i < 100);            // gate threads compute gates 2i, 2i+1

    // ---- weights: two gate rows of one matrix, f32x2-packed, zero-padded ----
    ull wA[26], wB[26];
    float2 bias2 = make_float2(0.0f, 0.0f);
    if (isG) {
        const float* wm = (grp == 0) ? w_hh0 : (grp == 1) ? w_ih1 : w_hh1;
        const int g0 = 2 * i, g1 = 2 * i + 1;
        #pragma unroll
        for (int k2 = 0; k2 < 26; k2++) {
            float a0 = (2 * k2     < H_) ? __ldg(&wm[g0 * H_ + 2 * k2])     : 0.0f;
            float a1 = (2 * k2 + 1 < H_) ? __ldg(&wm[g0 * H_ + 2 * k2 + 1]) : 0.0f;
            wA[k2] = pk2(a0, a1);
            float b0 = (2 * k2     < H_) ? __ldg(&wm[g1 * H_ + 2 * k2])     : 0.0f;
            float b1 = (2 * k2 + 1 < H_) ? __ldg(&wm[g1 * H_ + 2 * k2 + 1]) : 0.0f;
            wB[k2] = pk2(b0, b1);
        }
        if (grp == 1) {
            bias2.x = __ldg(&b_ih1[g0]) + __ldg(&b_hh1[g0]);
            bias2.y = __ldg(&b_ih1[g1]) + __ldg(&b_hh1[g1]);
        }
    }

    // gx prefetch registers (G0 gate threads): float2 per row (gates 2i, 2i+1)
    float2 gxr[NB];
    if (grp == 0 && isG) {
        #pragma unroll
        for (int r = 0; r < NB; r++)
            gxr[r] = *(const float2*)&g_gx[(size_t)(row0 + r) * G_ + 2 * i];  // t=0
    }

    // ---- zero h buffers (pads must stay 0) ----
    for (int k = tid; k < 2 * NB * 52; k += NTH) ((float*)hx)[k] = 0.0f;

    // ---- combine ownership: cell tid; plus cell tid+384 if tid<316 ----
    float c_st[2] = {0.0f, 0.0f};
    int   coff[2], hoff[2];
    bool  cl2[2];
    const bool has2 = (tid < NCELL - NTH);   // tid < 316
    #pragma unroll
    for (int k = 0; k < 2; k++) {
        const int cell = tid + k * NTH;
        cl2[k] = (cell >= NC1);
        const int rem = cl2[k] ? cell - NC1 : cell;
        const int r = rem / H_;
        const int j = rem - r * H_;
        coff[k] = r * G_ + j;
        hoff[k] = (cl2[k] ? NB * 52 : 0) + r * 52 + j;
    }
    __syncthreads();

    for (int it = 0; it <= T_; it++) {
        // ---- gate phase ----
        if (isG) {
            const int hs = (grp == 2) ? 1 : 0;
            float* dst = (grp == 0) ? &gl1[0][0] : (grp == 1) ? &pA[0][0] : &pB[0][0];

            // G0: prefetch next iter's gx while computing (latency hidden)
            float2 gxn[NB];
            if (grp == 0 && it + 1 < T_) {
                #pragma unroll
                for (int r = 0; r < NB; r++)
                    gxn[r] = *(const float2*)
                        &g_gx[((size_t)(it + 1) * B_ + row0 + r) * G_ + 2 * i];
            }

            #pragma unroll
            for (int r = 0; r < NB; r++) {
                ull e0, e1;
                if (grp == 0)      { e0 = pk2(gxr[r].x, 0.0f); e1 = pk2(gxr[r].y, 0.0f); }
                else if (grp == 1) { e0 = pk2(bias2.x, 0.0f);  e1 = pk2(bias2.y, 0.0f);  }
                else               { e0 = 0ull;                e1 = 0ull;                }
                ull o0 = 0ull, o1 = 0ull;

                // batch 1: quads 0..4
                ulonglong2 v[5];
                #pragma unroll
                for (int q = 0; q < 5; q++)
                    v[q] = *(const ulonglong2*)&hx[hs][r][4 * q];
                #pragma unroll
                for (int q = 0; q < 5; q++) {
                    fma2(e0, wA[2 * q],     v[q].x);
                    fma2(o0, wA[2 * q + 1], v[q].y);
                    fma2(e1, wB[2 * q],     v[q].x);
                    fma2(o1, wB[2 * q + 1], v[q].y);
                }
                // batch 2: quads 5..9
                #pragma unroll
                for (int q = 0; q < 5; q++)
                    v[q] = *(const ulonglong2*)&hx[hs][r][4 * (q + 5)];
                #pragma unroll
                for (int q = 0; q < 5; q++) {
                    fma2(e0, wA[2 * (q + 5)],     v[q].x);
                    fma2(o0, wA[2 * (q + 5) + 1], v[q].y);
                    fma2(e1, wB[2 * (q + 5)],     v[q].x);
                    fma2(o1, wB[2 * (q + 5) + 1], v[q].y);
                }
                // batch 3: quads 10..12
                #pragma unroll
                for (int q = 0; q < 3; q++)
                    v[q] = *(const ulonglong2*)&hx[hs][r][4 * (q + 10)];
                #pragma unroll
                for (int q = 0; q < 3; q++) {
                    fma2(e0, wA[2 * (q + 10)],     v[q].x);
                    fma2(o0, wA[2 * (q + 10) + 1], v[q].y);
                    fma2(e1, wB[2 * (q + 10)],     v[q].x);
                    fma2(o1, wB[2 * (q + 10) + 1], v[q].y);
                }
                *(float2*)&dst[r * G_ + 2 * i] =
                    make_float2(rsum(e0) + rsum(o0), rsum(e1) + rsum(o1));
            }

            if (grp == 0 && it + 1 < T_) {
                #pragma unroll
                for (int r = 0; r < NB; r++) gxr[r] = gxn[r];
            }
        }
        __syncthreads();

        // ---- combine: 1-2 cells per thread (gate order i, f, g, o) ----
        #pragma unroll
        for (int k = 0; k < 2; k++) {
            const bool own = (k == 0) || has2;
            if (own) {
                const bool act = cl2[k] ? (it >= 1) : (it < T_);
                if (act) {
                    const int o = coff[k];
                    float gi, gf, gg, go;
                    if (cl2[k]) {
                        const float* q1 = &pA[0][0];
                        const float* q2 = &pB[0][0];
                        gi = q1[o]           + q2[o];
                        gf = q1[o + H_]      + q2[o + H_];
                        gg = q1[o + 2 * H_]  + q2[o + 2 * H_];
                        go = q1[o + 3 * H_]  + q2[o + 3 * H_];
                    } else {
                        const float* q0 = &gl1[0][0];
                        gi = q0[o];
                        gf = q0[o + H_];
                        gg = q0[o + 2 * H_];
                        go = q0[o + 3 * H_];
                    }
                    const float ig = sigf(gi);
                    const float fg = sigf(gf);
                    const float gv = tanh_f(gg);
                    const float og = sigf(go);
                    c_st[k] = fg * c_st[k] + ig * gv;
                    ((float*)hx)[hoff[k]] = og * tanh_f(c_st[k]);
                }
            }
        }
        __syncthreads();
    }

    // ---- FC head: warps 0-6 each handle one batch row, shfl reduction ----
    const int wid  = tid / 32;
    const int lane = tid - wid * 32;
    if (wid < NB) {
        const int row = row0 + wid;
        if (row < B_) {
            float s = 0.0f;
            #pragma unroll
            for (int uu = 0; uu < 2; uu++) {
                const int u = lane + uu * 32;
                float a = __ldg(&fc1_b[u]);
                #pragma unroll
                for (int k = 0; k < H_; k++)
                    a += __ldg(&fc1_w[u * H_ + k]) * hx[1][wid][k];
                a = fmaxf(a, 0.0f);
                s += a * __ldg(&fc2_w[u]);
            }
            #pragma unroll
            for (int off = 16; off > 0; off >>= 1)
                s += __shfl_down_sync(0xffffffffu, s, off);
            if (lane == 0) out[row] = s + __ldg(&fc2_b[0]);
        }
    }
}

extern "C" void kernel_launch(void* const* d_in, const int* in_sizes, int n_in,
                              void* d_out, int out_size) {
    const float* x     = (const float*)d_in[0];
    const float* w_ih0 = (const float*)d_in[1];
    const float* w_hh0 = (const float*)d_in[2];
    const float* b_ih0 = (const float*)d_in[3];
    const float* b_hh0 = (const float*)d_in[4];
    const float* w_ih1 = (const float*)d_in[5];
    const float* w_hh1 = (const float*)d_in[6];
    const float* b_ih1 = (const float*)d_in[7];
    const float* b_hh1 = (const float*)d_in[8];
    const float* fc1_w = (const float*)d_in[9];
    const float* fc1_b = (const float*)d_in[10];
    const float* fc2_w = (const float*)d_in[11];
    const float* fc2_b = (const float*)d_in[12];
    float* out = (float*)d_out;

    dim3 xg_grid(T_ / TT, B_);
    xgate_kernel<<<xg_grid, 256>>>(x, w_ih0, b_ih0, b_hh0);

    const int grid = (B_ + NB - 1) / NB;   // 147
    fused_lstm_kernel<<<grid, NTH>>>(
        w_hh0, w_ih1, w_hh1, b_ih1, b_hh1,
        fc1_w, fc1_b, fc2_w, fc2_b, out);
}